// round 7
// baseline (speedup 1.0000x reference)
#include <cuda_runtime.h>
#include <cuda_bf16.h>
#include <cstdint>
#include <math.h>

#define TOKENS 8192
#define DMODEL 2048
#define NEXP   8
#define FFNH   8192
#define CAP    2048

#define BM 128
#define BN 256
#define BK 64
#define OFF_AH  0
#define OFF_AL  16384
#define OFF_BH  32768
#define OFF_BL  65536
#define STAGE_B 98304              /* A(16+16)KB + B(32+32)KB */
#define SMEM_BYTES (2 * STAGE_B)   /* 192 KB, 2 stages */

// ---------------- device scratch (no runtime allocation allowed) ----------------
__device__ int   g_idx[TOKENS];
__device__ float g_prob[TOKENS];
__device__ int   g_tok[NEXP * CAP];
__device__ int   g_count[NEXP];
__device__ __nv_bfloat16 g_x_hi[(size_t)TOKENS * DMODEL];
__device__ __nv_bfloat16 g_x_lo[(size_t)TOKENS * DMODEL];
__device__ __nv_bfloat16 g_w1_hi[(size_t)NEXP * FFNH * DMODEL];   // [e][h][m]  K-major
__device__ __nv_bfloat16 g_w1_lo[(size_t)NEXP * FFNH * DMODEL];
__device__ __nv_bfloat16 g_w2_hi[(size_t)NEXP * DMODEL * FFNH];   // [e][m][h]  K-major
__device__ __nv_bfloat16 g_w2_lo[(size_t)NEXP * DMODEL * FFNH];
__device__ __nv_bfloat16 g_h_hi[(size_t)NEXP * CAP * FFNH];       // [e][c][h]  K-major
__device__ __nv_bfloat16 g_h_lo[(size_t)NEXP * CAP * FFNH];

// ---------------- helpers ----------------
__device__ __forceinline__ uint32_t smem_u32(const void* p) {
    uint32_t a;
    asm("{ .reg .u64 t; cvta.to.shared.u64 t, %1; cvt.u32.u64 %0, t; }" : "=r"(a) : "l"(p));
    return a;
}
__device__ __forceinline__ void cp16(uint32_t dst, const void* src, uint32_t sz) {
    asm volatile("cp.async.cg.shared.global [%0], [%1], 16, %2;"
                 :: "r"(dst), "l"(src), "r"(sz) : "memory");
}
#define CP_COMMIT() asm volatile("cp.async.commit_group;" ::: "memory")
#define CP_WAIT1()  asm volatile("cp.async.wait_group 1;" ::: "memory")
#define CP_WAIT0()  asm volatile("cp.async.wait_group 0;" ::: "memory")

__device__ __forceinline__ void ldsm_x4(uint32_t& r0, uint32_t& r1, uint32_t& r2,
                                        uint32_t& r3, uint32_t a) {
    asm volatile("ldmatrix.sync.aligned.m8n8.x4.shared.b16 {%0,%1,%2,%3}, [%4];"
                 : "=r"(r0), "=r"(r1), "=r"(r2), "=r"(r3) : "r"(a));
}
__device__ __forceinline__ void ldsm_x2(uint32_t& r0, uint32_t& r1, uint32_t a) {
    asm volatile("ldmatrix.sync.aligned.m8n8.x2.shared.b16 {%0,%1}, [%2];"
                 : "=r"(r0), "=r"(r1) : "r"(a));
}
__device__ __forceinline__ void mma_bf16(float* c, const uint32_t* a, const uint32_t* b) {
    asm volatile(
        "mma.sync.aligned.m16n8k16.row.col.f32.bf16.bf16.f32 "
        "{%0,%1,%2,%3}, {%4,%5,%6,%7}, {%8,%9}, {%0,%1,%2,%3};"
        : "+f"(c[0]), "+f"(c[1]), "+f"(c[2]), "+f"(c[3])
        : "r"(a[0]), "r"(a[1]), "r"(a[2]), "r"(a[3]), "r"(b[0]), "r"(b[1]));
}

// hi/lo bf16 split: ~16 effective mantissa bits
__device__ __forceinline__ void split1(float f, unsigned short& h, unsigned short& l) {
    __nv_bfloat16 bh = __float2bfloat16(f);
    float rem = f - __bfloat162float(bh);
    __nv_bfloat16 bl = __float2bfloat16(rem);
    h = *reinterpret_cast<unsigned short*>(&bh);
    l = *reinterpret_cast<unsigned short*>(&bl);
}
// jax.nn.gelu default: approximate=True (tanh form)
__device__ __forceinline__ float gelu_tanh(float v) {
    float c = 0.7978845608028654f * (v + 0.044715f * v * v * v);
    return 0.5f * v * (1.0f + tanhf(c));
}

// ---------------- gate: logits = x @ Wg, softmax, argmax (1 warp / token) ----------------
__global__ void gate_kernel(const float* __restrict__ x, const float* __restrict__ Wg) {
    int tokw = (blockIdx.x * blockDim.x + threadIdx.x) >> 5;
    int lane = threadIdx.x & 31;
    if (tokw >= TOKENS) return;
    const float* xr = x + (size_t)tokw * DMODEL;
    float acc[NEXP];
#pragma unroll
    for (int e = 0; e < NEXP; e++) acc[e] = 0.f;
    for (int m = lane; m < DMODEL; m += 32) {
        float xv = xr[m];
        float4 w0 = *(const float4*)(Wg + m * NEXP);
        float4 w1 = *(const float4*)(Wg + m * NEXP + 4);
        acc[0] = fmaf(xv, w0.x, acc[0]); acc[1] = fmaf(xv, w0.y, acc[1]);
        acc[2] = fmaf(xv, w0.z, acc[2]); acc[3] = fmaf(xv, w0.w, acc[3]);
        acc[4] = fmaf(xv, w1.x, acc[4]); acc[5] = fmaf(xv, w1.y, acc[5]);
        acc[6] = fmaf(xv, w1.z, acc[6]); acc[7] = fmaf(xv, w1.w, acc[7]);
    }
#pragma unroll
    for (int e = 0; e < NEXP; e++)
#pragma unroll
        for (int o = 16; o > 0; o >>= 1)
            acc[e] += __shfl_xor_sync(0xffffffffu, acc[e], o);
    if (lane == 0) {
        float mx = acc[0]; int am = 0;
#pragma unroll
        for (int e = 1; e < NEXP; e++)
            if (acc[e] > mx) { mx = acc[e]; am = e; }   // strict > = first max (jnp.argmax)
        float s = 0.f;
#pragma unroll
        for (int e = 0; e < NEXP; e++) s += expf(acc[e] - mx);
        g_idx[tokw]  = am;
        g_prob[tokw] = 1.0f / s;
    }
}

// ---------------- routing scan (order-preserving cumsum, warp w = expert w) ----------------
__global__ void scan_kernel() {
    int w = threadIdx.x >> 5, lane = threadIdx.x & 31;
    int count = 0;
    for (int base = 0; base < TOKENS; base += 32) {
        int t = base + lane;
        int match = (g_idx[t] == w);
        unsigned mask = __ballot_sync(0xffffffffu, match);
        if (match) {
            int p = count + __popc(mask & ((1u << lane) - 1u));
            if (p < CAP) g_tok[w * CAP + p] = t;
        }
        count += __popc(mask);
    }
    if (lane == 0) g_count[w] = (count < CAP) ? count : CAP;
}

// ---------------- prep: split x -> bf16 hi/lo ----------------
__global__ void split_x_kernel(const float* __restrict__ x) {
    size_t i = ((size_t)blockIdx.x * blockDim.x + threadIdx.x) * 8;
    float4 a = *(const float4*)(x + i);
    float4 b = *(const float4*)(x + i + 4);
    float v[8] = {a.x, a.y, a.z, a.w, b.x, b.y, b.z, b.w};
    uint4 hi, lo;
    unsigned short* hp = (unsigned short*)&hi;
    unsigned short* lp = (unsigned short*)&lo;
#pragma unroll
    for (int q = 0; q < 8; q++) split1(v[q], hp[q], lp[q]);
    *(uint4*)(g_x_hi + i) = hi;
    *(uint4*)(g_x_lo + i) = lo;
}

// ---------------- prep: transpose + split weights to K-major bf16 ----------------
// WHICH=0: W1 [e][M][H] -> g_w1 [e][H][M];  WHICH=1: W2 [e][H][M] -> g_w2 [e][M][H]
template <int WHICH>
__global__ void transpose_split_kernel(const float* __restrict__ in) {
    constexpr int R = (WHICH == 0) ? DMODEL : FFNH;
    constexpr int C = (WHICH == 0) ? FFNH : DMODEL;
    __nv_bfloat16* ohi = (WHICH == 0) ? g_w1_hi : g_w2_hi;
    __nv_bfloat16* olo = (WHICH == 0) ? g_w1_lo : g_w2_lo;
    __shared__ float t[32][33];
    int e  = blockIdx.z;
    const float* ip = in + (size_t)e * R * C;
    size_t ob = (size_t)e * R * C;
    int c0 = blockIdx.x * 32, r0 = blockIdx.y * 32;
    int tx = threadIdx.x, ty = threadIdx.y;
#pragma unroll
    for (int i = 0; i < 32; i += 8)
        t[ty + i][tx] = ip[(size_t)(r0 + ty + i) * C + (c0 + tx)];
    __syncthreads();
#pragma unroll
    for (int i = 0; i < 32; i += 8) {
        float v = t[tx][ty + i];
        unsigned short h, l;
        split1(v, h, l);
        size_t o = ob + (size_t)(c0 + ty + i) * R + (r0 + tx);
        ohi[o] = *reinterpret_cast<__nv_bfloat16*>(&h);
        olo[o] = *reinterpret_cast<__nv_bfloat16*>(&l);
    }
}

// ---------------- grouped GEMM, HMMA bf16 2-term split (3 passes) ----------------
// CTA tile 128x256, warp tile 64x64, 2-stage cp.async pipeline.
// MODE 0: h[e] = gelu( gather(x_split) @ W1split[e] )   K=2048, N=8192
// MODE 1: out[tok] = ( h_split @ W2split[e] ) * prob    K=8192, N=2048
template <int MODE>
__global__ void __launch_bounds__(256, 1)
moe_gemm_mma(float* __restrict__ out) {
    constexpr int Ktot = (MODE == 0) ? DMODEL : FFNH;
    constexpr int nK   = Ktot / BK;

    extern __shared__ char smem[];
    const uint32_t sb = smem_u32(smem);
    const int tid  = threadIdx.x;
    const int lane = tid & 31;
    const int wid  = tid >> 5;
    const int e    = blockIdx.z;
    const int rows = g_count[e];
    const int row0 = blockIdx.x * BM;
    if (row0 >= rows) return;                 // count-limited: skip empty tiles
    const int col0 = blockIdx.y * BN;

    // ---- A loader: thread -> A row (tid>>1), 64-byte half (tid&1) ----
    const int lrow = tid >> 1;
    const int half = tid & 1;
    uint32_t aswo[4];
#pragma unroll
    for (int j = 0; j < 4; j++) {
        uint32_t u = (uint32_t)(half * 4 + j);
        aswo[j] = (uint32_t)lrow * 128u + ((u ^ ((uint32_t)lrow & 7u)) << 4);
    }
    // ---- B loader: thread -> full B row tid (128 bytes) ----
    uint32_t bswo[8];
#pragma unroll
    for (int u = 0; u < 8; u++)
        bswo[u] = (uint32_t)tid * 128u + (((uint32_t)u ^ ((uint32_t)tid & 7u)) << 4);

    const int  gr     = row0 + lrow;
    const bool avalid = gr < rows;
    const uint32_t asz = avalid ? 16u : 0u;
    const char *pAH, *pAL, *pBH, *pBL;
    if (MODE == 0) {
        int tok = avalid ? g_tok[e * CAP + gr] : 0;
        pAH = (const char*)(g_x_hi + (size_t)tok * DMODEL) + half * 64;
        pAL = (const char*)(g_x_lo + (size_t)tok * DMODEL) + half * 64;
        pBH = (const char*)(g_w1_hi + ((size_t)e * FFNH + col0 + tid) * DMODEL);
        pBL = (const char*)(g_w1_lo + ((size_t)e * FFNH + col0 + tid) * DMODEL);
    } else {
        pAH = (const char*)(g_h_hi + ((size_t)e * CAP + gr) * FFNH) + half * 64;
        pAL = (const char*)(g_h_lo + ((size_t)e * CAP + gr) * FFNH) + half * 64;
        pBH = (const char*)(g_w2_hi + ((size_t)e * DMODEL + col0 + tid) * FFNH);
        pBL = (const char*)(g_w2_lo + ((size_t)e * DMODEL + col0 + tid) * FFNH);
    }

    auto load_stage = [&](int kt) {
        uint32_t s = sb + (uint32_t)(kt & 1) * STAGE_B;
        size_t go = (size_t)kt * (BK * 2);          // byte offset along K
#pragma unroll
        for (int j = 0; j < 4; j++) cp16(s + OFF_AH + aswo[j], pAH + go + j * 16, asz);
#pragma unroll
        for (int j = 0; j < 4; j++) cp16(s + OFF_AL + aswo[j], pAL + go + j * 16, asz);
#pragma unroll
        for (int u = 0; u < 8; u++) cp16(s + OFF_BH + bswo[u], pBH + go + u * 16, 16u);
#pragma unroll
        for (int u = 0; u < 8; u++) cp16(s + OFF_BL + bswo[u], pBL + go + u * 16, 16u);
    };

    load_stage(0); CP_COMMIT();
    load_stage(1); CP_COMMIT();

    // ---- warp tiling: 2 (m) x 4 (n), warp tile 64x64 ----
    const int wm = (wid & 1) * 64;
    const int wn = (wid >> 1) * 64;

    // ldmatrix per-thread address pieces
    const int a_rloc = ((lane >> 3) & 1) * 8 + (lane & 7);   // row within 16-row m-tile
    const int a_kub  = lane >> 4;                            // 0/1: k-unit selector
    const int b_rloc = lane & 7;                             // row within 8-row n-tile
    const int b_kub  = (lane & 15) >> 3;

    float acc[4][8][4];
#pragma unroll
    for (int i = 0; i < 4; i++)
#pragma unroll
        for (int j = 0; j < 8; j++)
#pragma unroll
            for (int q = 0; q < 4; q++) acc[i][j][q] = 0.f;

    for (int kt = 0; kt < nK; kt++) {
        CP_WAIT1();                      // stage kt arrived (kt+1 may be pending)
        __syncthreads();

        const uint32_t s = sb + (uint32_t)(kt & 1) * STAGE_B;
#pragma unroll
        for (int ks = 0; ks < BK / 16; ks++) {
            uint32_t ah[4][4], al[4][4];
#pragma unroll
            for (int i = 0; i < 4; i++) {
                int row = wm + i * 16 + a_rloc;
                int u   = ks * 2 + a_kub;
                uint32_t off = (uint32_t)row * 128u + (((uint32_t)u ^ ((uint32_t)row & 7u)) << 4);
                ldsm_x4(ah[i][0], ah[i][1], ah[i][2], ah[i][3], s + OFF_AH + off);
                ldsm_x4(al[i][0], al[i][1], al[i][2], al[i][3], s + OFF_AL + off);
            }
            // B in two 32-col halves to cap fragment liveness
#pragma unroll
            for (int jh = 0; jh < 2; jh++) {
                uint32_t bh[4][2], bl[4][2];
#pragma unroll
                for (int j4 = 0; j4 < 4; j4++) {
                    int row = wn + jh * 32 + j4 * 8 + b_rloc;
                    int u   = ks * 2 + b_kub;
                    uint32_t off = (uint32_t)row * 128u + (((uint32_t)u ^ ((uint32_t)row & 7u)) << 4);
                    ldsm_x2(bh[j4][0], bh[j4][1], s + OFF_BH + off);
                    ldsm_x2(bl[j4][0], bl[j4][1], s + OFF_BL + off);
                }
                // pass 1: Ahi*Bhi, pass 2: Ahi*Blo, pass 3: Alo*Bhi
#pragma unroll
                for (int i = 0; i < 4; i++)
#pragma unroll
                    for (int j4 = 0; j4 < 4; j4++) mma_bf16(acc[i][jh * 4 + j4], ah[i], bh[j4]);
#pragma unroll
                for (int i = 0; i < 4; i++)
#pragma unroll
                    for (int j4 = 0; j4 < 4; j4++) mma_bf16(acc[i][jh * 4 + j4], ah[i], bl[j4]);
#pragma unroll
                for (int i = 0; i < 4; i++)
#pragma unroll
                    for (int j4 = 0; j4 < 4; j4++) mma_bf16(acc[i][jh * 4 + j4], al[i], bh[j4]);
            }
        }
        __syncthreads();                 // all warps done reading stage kt
        if (kt + 2 < nK) load_stage(kt + 2);
        CP_COMMIT();
    }
    CP_WAIT0();

    // ---- epilogue (register accumulators) ----
    // frag layout: c0=(m=g,n=tg*2) c1=(g,tg*2+1) c2=(g+8,tg*2) c3=(g+8,tg*2+1)
    const int g  = lane >> 2;
    const int tg = lane & 3;
#pragma unroll
    for (int i = 0; i < 4; i++) {
#pragma unroll
        for (int h2 = 0; h2 < 2; h2++) {
            int row = row0 + wm + i * 16 + g + h2 * 8;
            if (row >= rows) continue;
            if (MODE == 0) {
                size_t base = ((size_t)e * CAP + row) * FFNH;
#pragma unroll
                for (int j = 0; j < 8; j++) {
                    int c = col0 + wn + j * 8 + tg * 2;
                    float f0 = gelu_tanh(acc[i][j][h2 * 2 + 0]);
                    float f1 = gelu_tanh(acc[i][j][h2 * 2 + 1]);
                    unsigned short h0, l0, h1, l1;
                    split1(f0, h0, l0);
                    split1(f1, h1, l1);
                    *(uint32_t*)(g_h_hi + base + c) = (uint32_t)h0 | ((uint32_t)h1 << 16);
                    *(uint32_t*)(g_h_lo + base + c) = (uint32_t)l0 | ((uint32_t)l1 << 16);
                }
            } else {
                int   tok = g_tok[e * CAP + row];
                float gw  = g_prob[tok];
                float* dst = out + (size_t)tok * DMODEL;
#pragma unroll
                for (int j = 0; j < 8; j++) {
                    int c = col0 + wn + j * 8 + tg * 2;
                    float2 v;
                    v.x = acc[i][j][h2 * 2 + 0] * gw;
                    v.y = acc[i][j][h2 * 2 + 1] * gw;
                    *(float2*)(dst + c) = v;
                }
            }
        }
    }
}

// ---------------- launch ----------------
extern "C" void kernel_launch(void* const* d_in, const int* in_sizes, int n_in,
                              void* d_out, int out_size) {
    (void)in_sizes; (void)n_in;
    const float* x  = (const float*)d_in[0];   // [S, M]
    const float* Wg = (const float*)d_in[1];   // [M, E]
    const float* W1 = (const float*)d_in[2];   // [E, M, H]
    const float* W2 = (const float*)d_in[3];   // [E, H, M]
    float* out = (float*)d_out;                // [S, M]

    cudaFuncSetAttribute((const void*)moe_gemm_mma<0>,
                         cudaFuncAttributeMaxDynamicSharedMemorySize, SMEM_BYTES);
    cudaFuncSetAttribute((const void*)moe_gemm_mma<1>,
                         cudaFuncAttributeMaxDynamicSharedMemorySize, SMEM_BYTES);

    gate_kernel<<<TOKENS / 8, 256>>>(x, Wg);
    scan_kernel<<<1, 256>>>();
    split_x_kernel<<<(TOKENS * DMODEL) / (256 * 8), 256>>>(x);
    transpose_split_kernel<0><<<dim3(FFNH / 32, DMODEL / 32, NEXP), dim3(32, 8)>>>(W1);
    transpose_split_kernel<1><<<dim3(DMODEL / 32, FFNH / 32, NEXP), dim3(32, 8)>>>(W2);

    // grid.x = row tiles (fastest) so concurrent row-CTAs share each B tile in L2
    moe_gemm_mma<0><<<dim3(CAP / BM, FFNH / BN, NEXP), 256, SMEM_BYTES>>>(nullptr);
    cudaMemsetAsync(d_out, 0, (size_t)out_size * sizeof(float));   // dropped tokens -> 0
    moe_gemm_mma<1><<<dim3(CAP / BM, DMODEL / BN, NEXP), 256, SMEM_BYTES>>>(out);
}

// round 8
// speedup vs baseline: 1.1776x; 1.1776x over previous
#include <cuda_runtime.h>
#include <cuda_bf16.h>
#include <cstdint>
#include <math.h>

#define TOKENS 8192
#define DMODEL 2048
#define NEXP   8
#define FFNH   8192
#define CAP    2048

#define BM 128
#define BN 128
#define BK 64
#define STAGES 3
#define TILE_B  (BM * BK * 2)      /* 16384 bytes per operand tile */
#define OFF_AH  0
#define OFF_AL  (TILE_B)
#define OFF_BH  (2 * TILE_B)
#define OFF_BL  (3 * TILE_B)
#define STAGE_B (4 * TILE_B)       /* 65536 */
#define SMEM_BYTES (STAGES * STAGE_B)

// ---------------- device scratch (no runtime allocation allowed) ----------------
__device__ int   g_idx[TOKENS];
__device__ float g_prob[TOKENS];
__device__ int   g_tok[NEXP * CAP];
__device__ int   g_count[NEXP];
__device__ __nv_bfloat16 g_x_hi[(size_t)TOKENS * DMODEL];
__device__ __nv_bfloat16 g_x_lo[(size_t)TOKENS * DMODEL];
__device__ __nv_bfloat16 g_w1_hi[(size_t)NEXP * FFNH * DMODEL];   // [e][h][m]  K-major
__device__ __nv_bfloat16 g_w1_lo[(size_t)NEXP * FFNH * DMODEL];
__device__ __nv_bfloat16 g_w2_hi[(size_t)NEXP * DMODEL * FFNH];   // [e][m][h]  K-major
__device__ __nv_bfloat16 g_w2_lo[(size_t)NEXP * DMODEL * FFNH];
__device__ __nv_bfloat16 g_h_hi[(size_t)NEXP * CAP * FFNH];       // [e][c][h]  K-major
__device__ __nv_bfloat16 g_h_lo[(size_t)NEXP * CAP * FFNH];

// ---------------- helpers ----------------
__device__ __forceinline__ uint32_t smem_u32(const void* p) {
    uint32_t a;
    asm("{ .reg .u64 t; cvta.to.shared.u64 t, %1; cvt.u32.u64 %0, t; }" : "=r"(a) : "l"(p));
    return a;
}
__device__ __forceinline__ void cp16(uint32_t dst, const void* src, uint32_t sz) {
    asm volatile("cp.async.cg.shared.global [%0], [%1], 16, %2;"
                 :: "r"(dst), "l"(src), "r"(sz) : "memory");
}
#define CP_COMMIT() asm volatile("cp.async.commit_group;" ::: "memory")
#define CP_WAIT1()  asm volatile("cp.async.wait_group 1;" ::: "memory")
#define CP_WAIT0()  asm volatile("cp.async.wait_group 0;" ::: "memory")

__device__ __forceinline__ void ldsm_x4(uint32_t& r0, uint32_t& r1, uint32_t& r2,
                                        uint32_t& r3, uint32_t a) {
    asm volatile("ldmatrix.sync.aligned.m8n8.x4.shared.b16 {%0,%1,%2,%3}, [%4];"
                 : "=r"(r0), "=r"(r1), "=r"(r2), "=r"(r3) : "r"(a));
}
__device__ __forceinline__ void mma_bf16(float* c, const uint32_t* a, const uint32_t* b) {
    asm volatile(
        "mma.sync.aligned.m16n8k16.row.col.f32.bf16.bf16.f32 "
        "{%0,%1,%2,%3}, {%4,%5,%6,%7}, {%8,%9}, {%0,%1,%2,%3};"
        : "+f"(c[0]), "+f"(c[1]), "+f"(c[2]), "+f"(c[3])
        : "r"(a[0]), "r"(a[1]), "r"(a[2]), "r"(a[3]), "r"(b[0]), "r"(b[1]));
}

// hi/lo bf16 split: ~16 effective mantissa bits
__device__ __forceinline__ void split1(float f, unsigned short& h, unsigned short& l) {
    __nv_bfloat16 bh = __float2bfloat16(f);
    float rem = f - __bfloat162float(bh);
    __nv_bfloat16 bl = __float2bfloat16(rem);
    h = *reinterpret_cast<unsigned short*>(&bh);
    l = *reinterpret_cast<unsigned short*>(&bl);
}
// jax.nn.gelu default: approximate=True (tanh form)
__device__ __forceinline__ float gelu_tanh(float v) {
    float c = 0.7978845608028654f * (v + 0.044715f * v * v * v);
    return 0.5f * v * (1.0f + tanhf(c));
}

// ---------------- gate: logits = x @ Wg, softmax, argmax (1 warp / token) ----------------
__global__ void gate_kernel(const float* __restrict__ x, const float* __restrict__ Wg) {
    int tokw = (blockIdx.x * blockDim.x + threadIdx.x) >> 5;
    int lane = threadIdx.x & 31;
    if (tokw >= TOKENS) return;
    const float* xr = x + (size_t)tokw * DMODEL;
    float acc[NEXP];
#pragma unroll
    for (int e = 0; e < NEXP; e++) acc[e] = 0.f;
    for (int m = lane; m < DMODEL; m += 32) {
        float xv = xr[m];
        float4 w0 = *(const float4*)(Wg + m * NEXP);
        float4 w1 = *(const float4*)(Wg + m * NEXP + 4);
        acc[0] = fmaf(xv, w0.x, acc[0]); acc[1] = fmaf(xv, w0.y, acc[1]);
        acc[2] = fmaf(xv, w0.z, acc[2]); acc[3] = fmaf(xv, w0.w, acc[3]);
        acc[4] = fmaf(xv, w1.x, acc[4]); acc[5] = fmaf(xv, w1.y, acc[5]);
        acc[6] = fmaf(xv, w1.z, acc[6]); acc[7] = fmaf(xv, w1.w, acc[7]);
    }
#pragma unroll
    for (int e = 0; e < NEXP; e++)
#pragma unroll
        for (int o = 16; o > 0; o >>= 1)
            acc[e] += __shfl_xor_sync(0xffffffffu, acc[e], o);
    if (lane == 0) {
        float mx = acc[0]; int am = 0;
#pragma unroll
        for (int e = 1; e < NEXP; e++)
            if (acc[e] > mx) { mx = acc[e]; am = e; }   // strict > = first max (jnp.argmax)
        float s = 0.f;
#pragma unroll
        for (int e = 0; e < NEXP; e++) s += expf(acc[e] - mx);
        g_idx[tokw]  = am;
        g_prob[tokw] = 1.0f / s;
    }
}

// ---------------- routing scan (order-preserving cumsum, warp w = expert w) ----------------
__global__ void scan_kernel() {
    int w = threadIdx.x >> 5, lane = threadIdx.x & 31;
    int count = 0;
    for (int base = 0; base < TOKENS; base += 32) {
        int t = base + lane;
        int match = (g_idx[t] == w);
        unsigned mask = __ballot_sync(0xffffffffu, match);
        if (match) {
            int p = count + __popc(mask & ((1u << lane) - 1u));
            if (p < CAP) g_tok[w * CAP + p] = t;
        }
        count += __popc(mask);
    }
    if (lane == 0) g_count[w] = (count < CAP) ? count : CAP;
}

// ---------------- prep: split x -> bf16 hi/lo ----------------
__global__ void split_x_kernel(const float* __restrict__ x) {
    size_t i = ((size_t)blockIdx.x * blockDim.x + threadIdx.x) * 8;
    float4 a = *(const float4*)(x + i);
    float4 b = *(const float4*)(x + i + 4);
    float v[8] = {a.x, a.y, a.z, a.w, b.x, b.y, b.z, b.w};
    uint4 hi, lo;
    unsigned short* hp = (unsigned short*)&hi;
    unsigned short* lp = (unsigned short*)&lo;
#pragma unroll
    for (int q = 0; q < 8; q++) split1(v[q], hp[q], lp[q]);
    *(uint4*)(g_x_hi + i) = hi;
    *(uint4*)(g_x_lo + i) = lo;
}

// ---------------- prep: transpose + split weights to K-major bf16 ----------------
// 64x64 tiles, paired bf16 writes (128B per warp store transaction).
// WHICH=0: W1 [e][M][H] -> g_w1 [e][H][M];  WHICH=1: W2 [e][H][M] -> g_w2 [e][M][H]
template <int WHICH>
__global__ void __launch_bounds__(256)
transpose_split_kernel(const float* __restrict__ in) {
    constexpr int Rin = (WHICH == 0) ? DMODEL : FFNH;   // input rows
    constexpr int Cin = (WHICH == 0) ? FFNH : DMODEL;   // input cols
    __nv_bfloat16* ohi = (WHICH == 0) ? g_w1_hi : g_w2_hi;
    __nv_bfloat16* olo = (WHICH == 0) ? g_w1_lo : g_w2_lo;
    __shared__ float t[64][65];
    const int e  = blockIdx.z;
    const float* ip = in + (size_t)e * Rin * Cin;
    const size_t ob = (size_t)e * Rin * Cin;
    const int c0 = blockIdx.x * 64, r0 = blockIdx.y * 64;
    const int tid = threadIdx.x;

    // read: 64 rows x 64 cols, float4 per thread per pass
    const int rr = tid >> 4;
    const int cc = (tid & 15) * 4;
#pragma unroll
    for (int i = 0; i < 4; i++) {
        int row = rr + i * 16;
        float4 v = *(const float4*)(ip + (size_t)(r0 + row) * Cin + c0 + cc);
        t[row][cc + 0] = v.x; t[row][cc + 1] = v.y;
        t[row][cc + 2] = v.z; t[row][cc + 3] = v.w;
    }
    __syncthreads();

    // write: warp w owns output row p*8+w; lane packs 2 consecutive bf16 (4B store)
    const int w = tid >> 5, l = tid & 31;
#pragma unroll
    for (int p = 0; p < 8; p++) {
        int orow = p * 8 + w;                 // source column
        float v0 = t[2 * l][orow];
        float v1 = t[2 * l + 1][orow];
        unsigned short h0, l0, h1, l1;
        split1(v0, h0, l0);
        split1(v1, h1, l1);
        size_t o = ob + (size_t)(c0 + orow) * Rin + r0 + 2 * l;
        *(uint32_t*)(ohi + o) = (uint32_t)h0 | ((uint32_t)h1 << 16);
        *(uint32_t*)(olo + o) = (uint32_t)l0 | ((uint32_t)l1 << 16);
    }
}

// ---------------- grouped GEMM, HMMA bf16 2-term split (3 passes) ----------------
// CTA tile 128x128, warp tile 64x32, 3-stage cp.async pipeline (R6-proven shape).
// MODE 0: h[e] = gelu( gather(x_split) @ W1split[e] )   K=2048, N=8192
// MODE 1: out[tok] = ( h_split @ W2split[e] ) * prob    K=8192, N=2048
template <int MODE>
__global__ void __launch_bounds__(256, 1)
moe_gemm_mma(float* __restrict__ out) {
    constexpr int Ktot = (MODE == 0) ? DMODEL : FFNH;
    constexpr int nK   = Ktot / BK;

    extern __shared__ char smem[];
    const uint32_t sb = smem_u32(smem);
    const int tid  = threadIdx.x;
    const int lane = tid & 31;
    const int wid  = tid >> 5;
    const int e    = blockIdx.z;
    const int rows = g_count[e];
    const int row0 = blockIdx.x * BM;
    if (row0 >= rows) return;                 // count-limited: skip empty tiles
    const int col0 = blockIdx.y * BN;

    // ---- loader: thread -> smem row (tid>>1), 64-byte half (tid&1) ----
    const int lrow = tid >> 1;
    const int half = tid & 1;
    uint32_t swo[4];
#pragma unroll
    for (int j = 0; j < 4; j++) {
        uint32_t u = (uint32_t)(half * 4 + j);
        swo[j] = (uint32_t)lrow * 128u + ((u ^ ((uint32_t)lrow & 7u)) << 4);
    }
    const int  gr     = row0 + lrow;
    const bool avalid = gr < rows;
    const uint32_t asz = avalid ? 16u : 0u;
    const char *pAH, *pAL, *pBH, *pBL;
    if (MODE == 0) {
        int tok = avalid ? g_tok[e * CAP + gr] : 0;
        pAH = (const char*)(g_x_hi + (size_t)tok * DMODEL) + half * 64;
        pAL = (const char*)(g_x_lo + (size_t)tok * DMODEL) + half * 64;
        pBH = (const char*)(g_w1_hi + ((size_t)e * FFNH + col0 + lrow) * DMODEL) + half * 64;
        pBL = (const char*)(g_w1_lo + ((size_t)e * FFNH + col0 + lrow) * DMODEL) + half * 64;
    } else {
        pAH = (const char*)(g_h_hi + ((size_t)e * CAP + gr) * FFNH) + half * 64;
        pAL = (const char*)(g_h_lo + ((size_t)e * CAP + gr) * FFNH) + half * 64;
        pBH = (const char*)(g_w2_hi + ((size_t)e * DMODEL + col0 + lrow) * FFNH) + half * 64;
        pBL = (const char*)(g_w2_lo + ((size_t)e * DMODEL + col0 + lrow) * FFNH) + half * 64;
    }

    auto load_stage = [&](int kt) {
        uint32_t s = sb + (uint32_t)(kt % STAGES) * STAGE_B;
        size_t go = (size_t)kt * (BK * 2);          // byte offset along K
#pragma unroll
        for (int j = 0; j < 4; j++) cp16(s + OFF_AH + swo[j], pAH + go + j * 16, asz);
#pragma unroll
        for (int j = 0; j < 4; j++) cp16(s + OFF_AL + swo[j], pAL + go + j * 16, asz);
#pragma unroll
        for (int j = 0; j < 4; j++) cp16(s + OFF_BH + swo[j], pBH + go + j * 16, 16u);
#pragma unroll
        for (int j = 0; j < 4; j++) cp16(s + OFF_BL + swo[j], pBL + go + j * 16, 16u);
    };

    load_stage(0); CP_COMMIT();
    load_stage(1); CP_COMMIT();

    // ---- warp tiling: 2 (m) x 4 (n), warp tile 64x32 ----
    const int wm = (wid & 1) * 64;
    const int wn = (wid >> 1) * 32;

    // ldmatrix per-thread address pieces
    const int a_rloc = ((lane >> 3) & 1) * 8 + (lane & 7);   // row within 16-row m-tile
    const int a_kub  = lane >> 4;                            // 0/1: k-unit selector
    // B x4 pairing: lanes 0-7 -> (n-tile j,   u0), 8-15 -> (j,   u1),
    //               lanes 16-23 -> (j+1, u0), 24-31 -> (j+1, u1)
    const int b_jj   = lane >> 4;                            // 0/1: n-tile within pair
    const int b_ku   = (lane >> 3) & 1;                      // 0/1: k-unit selector
    const int b_rloc = lane & 7;

    float acc[4][4][4];
#pragma unroll
    for (int i = 0; i < 4; i++)
#pragma unroll
        for (int j = 0; j < 4; j++)
#pragma unroll
            for (int q = 0; q < 4; q++) acc[i][j][q] = 0.f;

    for (int kt = 0; kt < nK; kt++) {
        CP_WAIT1();                      // stage kt arrived
        __syncthreads();
        if (kt + 2 < nK) load_stage(kt + 2);
        CP_COMMIT();

        const uint32_t s = sb + (uint32_t)(kt % STAGES) * STAGE_B;
#pragma unroll
        for (int ks = 0; ks < BK / 16; ks++) {
            uint32_t ah[4][4], al[4][4];
#pragma unroll
            for (int i = 0; i < 4; i++) {
                int row = wm + i * 16 + a_rloc;
                int u   = ks * 2 + a_kub;
                uint32_t off = (uint32_t)row * 128u + (((uint32_t)u ^ ((uint32_t)row & 7u)) << 4);
                ldsm_x4(ah[i][0], ah[i][1], ah[i][2], ah[i][3], s + OFF_AH + off);
                ldsm_x4(al[i][0], al[i][1], al[i][2], al[i][3], s + OFF_AL + off);
            }
            uint32_t bh[4][2], bl[4][2];
#pragma unroll
            for (int jp = 0; jp < 2; jp++) {      // n-tile pairs {0,1} and {2,3}
                int j   = jp * 2;
                int row = wn + (j + b_jj) * 8 + b_rloc;
                int u   = ks * 2 + b_ku;
                uint32_t off = (uint32_t)row * 128u + (((uint32_t)u ^ ((uint32_t)row & 7u)) << 4);
                ldsm_x4(bh[j][0], bh[j][1], bh[j + 1][0], bh[j + 1][1], s + OFF_BH + off);
                ldsm_x4(bl[j][0], bl[j][1], bl[j + 1][0], bl[j + 1][1], s + OFF_BL + off);
            }
            // pass 1: Ahi*Bhi, pass 2: Ahi*Blo, pass 3: Alo*Bhi
            // (RAW distance on each acc = 16 MMAs)
#pragma unroll
            for (int i = 0; i < 4; i++)
#pragma unroll
                for (int j = 0; j < 4; j++) mma_bf16(acc[i][j], ah[i], bh[j]);
#pragma unroll
            for (int i = 0; i < 4; i++)
#pragma unroll
                for (int j = 0; j < 4; j++) mma_bf16(acc[i][j], ah[i], bl[j]);
#pragma unroll
            for (int i = 0; i < 4; i++)
#pragma unroll
                for (int j = 0; j < 4; j++) mma_bf16(acc[i][j], al[i], bh[j]);
        }
    }
    CP_WAIT0();

    // ---- epilogue (register accumulators) ----
    // frag layout: c0=(m=g,n=tg*2) c1=(g,tg*2+1) c2=(g+8,tg*2) c3=(g+8,tg*2+1)
    const int g  = lane >> 2;
    const int tg = lane & 3;
#pragma unroll
    for (int i = 0; i < 4; i++) {
#pragma unroll
        for (int h2 = 0; h2 < 2; h2++) {
            int row = row0 + wm + i * 16 + g + h2 * 8;
            if (row >= rows) continue;
            if (MODE == 0) {
                size_t base = ((size_t)e * CAP + row) * FFNH;
#pragma unroll
                for (int j = 0; j < 4; j++) {
                    int c = col0 + wn + j * 8 + tg * 2;
                    float f0 = gelu_tanh(acc[i][j][h2 * 2 + 0]);
                    float f1 = gelu_tanh(acc[i][j][h2 * 2 + 1]);
                    unsigned short h0, l0, h1, l1;
                    split1(f0, h0, l0);
                    split1(f1, h1, l1);
                    *(uint32_t*)(g_h_hi + base + c) = (uint32_t)h0 | ((uint32_t)h1 << 16);
                    *(uint32_t*)(g_h_lo + base + c) = (uint32_t)l0 | ((uint32_t)l1 << 16);
                }
            } else {
                int   tok = g_tok[e * CAP + row];
                float gw  = g_prob[tok];
                float* dst = out + (size_t)tok * DMODEL;
#pragma unroll
                for (int j = 0; j < 4; j++) {
                    int c = col0 + wn + j * 8 + tg * 2;
                    float2 v;
                    v.x = acc[i][j][h2 * 2 + 0] * gw;
                    v.y = acc[i][j][h2 * 2 + 1] * gw;
                    *(float2*)(dst + c) = v;
                }
            }
        }
    }
}

// ---------------- launch ----------------
extern "C" void kernel_launch(void* const* d_in, const int* in_sizes, int n_in,
                              void* d_out, int out_size) {
    (void)in_sizes; (void)n_in;
    const float* x  = (const float*)d_in[0];   // [S, M]
    const float* Wg = (const float*)d_in[1];   // [M, E]
    const float* W1 = (const float*)d_in[2];   // [E, M, H]
    const float* W2 = (const float*)d_in[3];   // [E, H, M]
    float* out = (float*)d_out;                // [S, M]

    cudaFuncSetAttribute((const void*)moe_gemm_mma<0>,
                         cudaFuncAttributeMaxDynamicSharedMemorySize, SMEM_BYTES);
    cudaFuncSetAttribute((const void*)moe_gemm_mma<1>,
                         cudaFuncAttributeMaxDynamicSharedMemorySize, SMEM_BYTES);

    gate_kernel<<<TOKENS / 8, 256>>>(x, Wg);
    scan_kernel<<<1, 256>>>();
    split_x_kernel<<<(TOKENS * DMODEL) / (256 * 8), 256>>>(x);
    transpose_split_kernel<0><<<dim3(FFNH / 64, DMODEL / 64, NEXP), 256>>>(W1);
    transpose_split_kernel<1><<<dim3(DMODEL / 64, FFNH / 64, NEXP), 256>>>(W2);

    // grid.x = row tiles (fastest) so concurrent row-CTAs share each B tile in L2
    moe_gemm_mma<0><<<dim3(CAP / BM, FFNH / BN, NEXP), 256, SMEM_BYTES>>>(nullptr);
    cudaMemsetAsync(d_out, 0, (size_t)out_size * sizeof(float));   // dropped tokens -> 0
    moe_gemm_mma<1><<<dim3(CAP / BM, DMODEL / BN, NEXP), 256, SMEM_BYTES>>>(out);
}

// round 9
// speedup vs baseline: 1.6214x; 1.3769x over previous
#include <cuda_runtime.h>
#include <cuda_fp16.h>
#include <cstdint>
#include <math.h>

#define TOKENS 8192
#define DMODEL 2048
#define NEXP   8
#define FFNH   8192
#define CAP    2048

#define BM 128
#define BN 128
#define BK 64
#define STAGES 3
#define TILE_B  (BM * BK * 2)      /* 16384 bytes per operand tile */
#define OFF_AH  0
#define OFF_AL  (TILE_B)
#define OFF_BH  (2 * TILE_B)
#define STAGE_B (3 * TILE_B)       /* 49152 */
#define SMEM_BYTES (STAGES * STAGE_B)   /* 144 KB */

// ---------------- device scratch (no runtime allocation allowed) ----------------
__device__ int   g_idx[TOKENS];
__device__ float g_prob[TOKENS];
__device__ int   g_tok[NEXP * CAP];
__device__ int   g_count[NEXP];
__device__ __half g_x_hi[(size_t)TOKENS * DMODEL];
__device__ __half g_x_lo[(size_t)TOKENS * DMODEL];
__device__ __half g_w1_hi[(size_t)NEXP * FFNH * DMODEL];   // [e][h][m]  K-major
__device__ __half g_w2_hi[(size_t)NEXP * DMODEL * FFNH];   // [e][m][h]  K-major
__device__ __half g_h_hi[(size_t)NEXP * CAP * FFNH];       // [e][c][h]  K-major
__device__ __half g_h_lo[(size_t)NEXP * CAP * FFNH];

// ---------------- helpers ----------------
__device__ __forceinline__ uint32_t smem_u32(const void* p) {
    uint32_t a;
    asm("{ .reg .u64 t; cvta.to.shared.u64 t, %1; cvt.u32.u64 %0, t; }" : "=r"(a) : "l"(p));
    return a;
}
__device__ __forceinline__ void cp16(uint32_t dst, const void* src, uint32_t sz) {
    asm volatile("cp.async.cg.shared.global [%0], [%1], 16, %2;"
                 :: "r"(dst), "l"(src), "r"(sz) : "memory");
}
#define CP_COMMIT() asm volatile("cp.async.commit_group;" ::: "memory")
#define CP_WAIT1()  asm volatile("cp.async.wait_group 1;" ::: "memory")
#define CP_WAIT0()  asm volatile("cp.async.wait_group 0;" ::: "memory")

__device__ __forceinline__ void ldsm_x4(uint32_t& r0, uint32_t& r1, uint32_t& r2,
                                        uint32_t& r3, uint32_t a) {
    asm volatile("ldmatrix.sync.aligned.m8n8.x4.shared.b16 {%0,%1,%2,%3}, [%4];"
                 : "=r"(r0), "=r"(r1), "=r"(r2), "=r"(r3) : "r"(a));
}
__device__ __forceinline__ void mma_f16(float* c, const uint32_t* a, const uint32_t* b) {
    asm volatile(
        "mma.sync.aligned.m16n8k16.row.col.f32.f16.f16.f32 "
        "{%0,%1,%2,%3}, {%4,%5,%6,%7}, {%8,%9}, {%0,%1,%2,%3};"
        : "+f"(c[0]), "+f"(c[1]), "+f"(c[2]), "+f"(c[3])
        : "r"(a[0]), "r"(a[1]), "r"(a[2]), "r"(a[3]), "r"(b[0]), "r"(b[1]));
}

// fp16 hi/lo split: ~22 effective mantissa bits
__device__ __forceinline__ void split1h(float f, unsigned short& h, unsigned short& l) {
    __half hh = __float2half_rn(f);
    float rem = f - __half2float(hh);
    __half ll = __float2half_rn(rem);
    h = __half_as_ushort(hh);
    l = __half_as_ushort(ll);
}
__device__ __forceinline__ unsigned short cvt_h(float f) {
    return __half_as_ushort(__float2half_rn(f));
}
// jax.nn.gelu default: approximate=True (tanh form)
__device__ __forceinline__ float gelu_tanh(float v) {
    float c = 0.7978845608028654f * (v + 0.044715f * v * v * v);
    return 0.5f * v * (1.0f + tanhf(c));
}

// ---------------- gate: logits = x @ Wg, softmax, argmax (1 warp / token) ----------------
__global__ void gate_kernel(const float* __restrict__ x, const float* __restrict__ Wg) {
    int tokw = (blockIdx.x * blockDim.x + threadIdx.x) >> 5;
    int lane = threadIdx.x & 31;
    if (tokw >= TOKENS) return;
    const float* xr = x + (size_t)tokw * DMODEL;
    float acc[NEXP];
#pragma unroll
    for (int e = 0; e < NEXP; e++) acc[e] = 0.f;
    for (int m = lane; m < DMODEL; m += 32) {
        float xv = xr[m];
        float4 w0 = *(const float4*)(Wg + m * NEXP);
        float4 w1 = *(const float4*)(Wg + m * NEXP + 4);
        acc[0] = fmaf(xv, w0.x, acc[0]); acc[1] = fmaf(xv, w0.y, acc[1]);
        acc[2] = fmaf(xv, w0.z, acc[2]); acc[3] = fmaf(xv, w0.w, acc[3]);
        acc[4] = fmaf(xv, w1.x, acc[4]); acc[5] = fmaf(xv, w1.y, acc[5]);
        acc[6] = fmaf(xv, w1.z, acc[6]); acc[7] = fmaf(xv, w1.w, acc[7]);
    }
#pragma unroll
    for (int e = 0; e < NEXP; e++)
#pragma unroll
        for (int o = 16; o > 0; o >>= 1)
            acc[e] += __shfl_xor_sync(0xffffffffu, acc[e], o);
    if (lane == 0) {
        float mx = acc[0]; int am = 0;
#pragma unroll
        for (int e = 1; e < NEXP; e++)
            if (acc[e] > mx) { mx = acc[e]; am = e; }   // strict > = first max (jnp.argmax)
        float s = 0.f;
#pragma unroll
        for (int e = 0; e < NEXP; e++) s += expf(acc[e] - mx);
        g_idx[tokw]  = am;
        g_prob[tokw] = 1.0f / s;
    }
}

// ---------------- routing scan (order-preserving cumsum, warp w = expert w) ----------------
__global__ void scan_kernel() {
    int w = threadIdx.x >> 5, lane = threadIdx.x & 31;
    int count = 0;
    for (int base = 0; base < TOKENS; base += 32) {
        int t = base + lane;
        int match = (g_idx[t] == w);
        unsigned mask = __ballot_sync(0xffffffffu, match);
        if (match) {
            int p = count + __popc(mask & ((1u << lane) - 1u));
            if (p < CAP) g_tok[w * CAP + p] = t;
        }
        count += __popc(mask);
    }
    if (lane == 0) g_count[w] = (count < CAP) ? count : CAP;
}

// ---------------- prep: split x -> fp16 hi/lo ----------------
__global__ void split_x_kernel(const float* __restrict__ x) {
    size_t i = ((size_t)blockIdx.x * blockDim.x + threadIdx.x) * 8;
    float4 a = *(const float4*)(x + i);
    float4 b = *(const float4*)(x + i + 4);
    float v[8] = {a.x, a.y, a.z, a.w, b.x, b.y, b.z, b.w};
    uint4 hi, lo;
    unsigned short* hp = (unsigned short*)&hi;
    unsigned short* lp = (unsigned short*)&lo;
#pragma unroll
    for (int q = 0; q < 8; q++) split1h(v[q], hp[q], lp[q]);
    *(uint4*)(g_x_hi + i) = hi;
    *(uint4*)(g_x_lo + i) = lo;
}

// ---------------- prep: transpose + convert weights to K-major fp16 (hi only) ----------
// 64x64 tiles, paired fp16 writes (128B per warp store transaction).
// WHICH=0: W1 [e][M][H] -> g_w1 [e][H][M];  WHICH=1: W2 [e][H][M] -> g_w2 [e][M][H]
template <int WHICH>
__global__ void __launch_bounds__(256)
transpose_split_kernel(const float* __restrict__ in) {
    constexpr int Rin = (WHICH == 0) ? DMODEL : FFNH;   // input rows
    constexpr int Cin = (WHICH == 0) ? FFNH : DMODEL;   // input cols
    __half* ohi = (WHICH == 0) ? g_w1_hi : g_w2_hi;
    __shared__ float t[64][65];
    const int e  = blockIdx.z;
    const float* ip = in + (size_t)e * Rin * Cin;
    const size_t ob = (size_t)e * Rin * Cin;
    const int c0 = blockIdx.x * 64, r0 = blockIdx.y * 64;
    const int tid = threadIdx.x;

    // read: 64 rows x 64 cols, float4 per thread per pass
    const int rr = tid >> 4;
    const int cc = (tid & 15) * 4;
#pragma unroll
    for (int i = 0; i < 4; i++) {
        int row = rr + i * 16;
        float4 v = *(const float4*)(ip + (size_t)(r0 + row) * Cin + c0 + cc);
        t[row][cc + 0] = v.x; t[row][cc + 1] = v.y;
        t[row][cc + 2] = v.z; t[row][cc + 3] = v.w;
    }
    __syncthreads();

    // write: warp w owns output row p*8+w; lane packs 2 consecutive fp16 (4B store)
    const int w = tid >> 5, l = tid & 31;
#pragma unroll
    for (int p = 0; p < 8; p++) {
        int orow = p * 8 + w;                 // source column
        unsigned short h0 = cvt_h(t[2 * l][orow]);
        unsigned short h1 = cvt_h(t[2 * l + 1][orow]);
        size_t o = ob + (size_t)(c0 + orow) * Rin + r0 + 2 * l;
        *(uint32_t*)(ohi + o) = (uint32_t)h0 | ((uint32_t)h1 << 16);
    }
}

// ---------------- grouped GEMM, HMMA fp16 A-split (2 passes: Ahi*B + Alo*B) ----------
// CTA tile 128x128, warp tile 64x32, 3-stage cp.async pipeline (proven shape).
// MODE 0: h[e] = gelu( gather(x_split) @ W1h[e] )   K=2048, N=8192
// MODE 1: out[tok] = ( h_split @ W2h[e] ) * prob    K=8192, N=2048
template <int MODE>
__global__ void __launch_bounds__(256, 1)
moe_gemm_mma(float* __restrict__ out) {
    constexpr int Ktot = (MODE == 0) ? DMODEL : FFNH;
    constexpr int nK   = Ktot / BK;

    extern __shared__ char smem[];
    const uint32_t sb = smem_u32(smem);
    const int tid  = threadIdx.x;
    const int lane = tid & 31;
    const int wid  = tid >> 5;
    const int e    = blockIdx.z;
    const int rows = g_count[e];
    const int row0 = blockIdx.x * BM;
    if (row0 >= rows) return;                 // count-limited: skip empty tiles
    const int col0 = blockIdx.y * BN;

    // ---- loader: thread -> smem row (tid>>1), 64-byte half (tid&1) ----
    const int lrow = tid >> 1;
    const int half = tid & 1;
    uint32_t swo[4];
#pragma unroll
    for (int j = 0; j < 4; j++) {
        uint32_t u = (uint32_t)(half * 4 + j);
        swo[j] = (uint32_t)lrow * 128u + ((u ^ ((uint32_t)lrow & 7u)) << 4);
    }
    const int  gr     = row0 + lrow;
    const bool avalid = gr < rows;
    const uint32_t asz = avalid ? 16u : 0u;
    const char *pAH, *pAL, *pBH;
    if (MODE == 0) {
        int tok = avalid ? g_tok[e * CAP + gr] : 0;
        pAH = (const char*)(g_x_hi + (size_t)tok * DMODEL) + half * 64;
        pAL = (const char*)(g_x_lo + (size_t)tok * DMODEL) + half * 64;
        pBH = (const char*)(g_w1_hi + ((size_t)e * FFNH + col0 + lrow) * DMODEL) + half * 64;
    } else {
        pAH = (const char*)(g_h_hi + ((size_t)e * CAP + gr) * FFNH) + half * 64;
        pAL = (const char*)(g_h_lo + ((size_t)e * CAP + gr) * FFNH) + half * 64;
        pBH = (const char*)(g_w2_hi + ((size_t)e * DMODEL + col0 + lrow) * FFNH) + half * 64;
    }

    auto load_stage = [&](int kt) {
        uint32_t s = sb + (uint32_t)(kt % STAGES) * STAGE_B;
        size_t go = (size_t)kt * (BK * 2);          // byte offset along K
#pragma unroll
        for (int j = 0; j < 4; j++) cp16(s + OFF_AH + swo[j], pAH + go + j * 16, asz);
#pragma unroll
        for (int j = 0; j < 4; j++) cp16(s + OFF_AL + swo[j], pAL + go + j * 16, asz);
#pragma unroll
        for (int j = 0; j < 4; j++) cp16(s + OFF_BH + swo[j], pBH + go + j * 16, 16u);
    };

    load_stage(0); CP_COMMIT();
    load_stage(1); CP_COMMIT();

    // ---- warp tiling: 2 (m) x 4 (n), warp tile 64x32 ----
    const int wm = (wid & 1) * 64;
    const int wn = (wid >> 1) * 32;

    // ldmatrix per-thread address pieces
    const int a_rloc = ((lane >> 3) & 1) * 8 + (lane & 7);   // row within 16-row m-tile
    const int a_kub  = lane >> 4;                            // 0/1: k-unit selector
    // B x4 pairing: lanes 0-7 -> (n-tile j, u0), 8-15 -> (j, u1),
    //               16-23 -> (j+1, u0), 24-31 -> (j+1, u1)
    const int b_jj   = lane >> 4;
    const int b_ku   = (lane >> 3) & 1;
    const int b_rloc = lane & 7;

    float acc[4][4][4];
#pragma unroll
    for (int i = 0; i < 4; i++)
#pragma unroll
        for (int j = 0; j < 4; j++)
#pragma unroll
            for (int q = 0; q < 4; q++) acc[i][j][q] = 0.f;

    for (int kt = 0; kt < nK; kt++) {
        CP_WAIT1();                      // stage kt arrived
        __syncthreads();
        if (kt + 2 < nK) load_stage(kt + 2);
        CP_COMMIT();

        const uint32_t s = sb + (uint32_t)(kt % STAGES) * STAGE_B;
#pragma unroll
        for (int ks = 0; ks < BK / 16; ks++) {
            uint32_t ah[4][4], al[4][4];
#pragma unroll
            for (int i = 0; i < 4; i++) {
                int row = wm + i * 16 + a_rloc;
                int u   = ks * 2 + a_kub;
                uint32_t off = (uint32_t)row * 128u + (((uint32_t)u ^ ((uint32_t)row & 7u)) << 4);
                ldsm_x4(ah[i][0], ah[i][1], ah[i][2], ah[i][3], s + OFF_AH + off);
                ldsm_x4(al[i][0], al[i][1], al[i][2], al[i][3], s + OFF_AL + off);
            }
            uint32_t bh[4][2];
#pragma unroll
            for (int jp = 0; jp < 2; jp++) {      // n-tile pairs {0,1} and {2,3}
                int j   = jp * 2;
                int row = wn + (j + b_jj) * 8 + b_rloc;
                int u   = ks * 2 + b_ku;
                uint32_t off = (uint32_t)row * 128u + (((uint32_t)u ^ ((uint32_t)row & 7u)) << 4);
                ldsm_x4(bh[j][0], bh[j][1], bh[j + 1][0], bh[j + 1][1], s + OFF_BH + off);
            }
            // pass 1: Ahi*B, pass 2: Alo*B   (A ~22-bit via hi+lo; error ~ B fp16 rounding)
#pragma unroll
            for (int i = 0; i < 4; i++)
#pragma unroll
                for (int j = 0; j < 4; j++) mma_f16(acc[i][j], ah[i], bh[j]);
#pragma unroll
            for (int i = 0; i < 4; i++)
#pragma unroll
                for (int j = 0; j < 4; j++) mma_f16(acc[i][j], al[i], bh[j]);
        }
    }
    CP_WAIT0();

    // ---- epilogue (register accumulators) ----
    // frag layout: c0=(m=g,n=tg*2) c1=(g,tg*2+1) c2=(g+8,tg*2) c3=(g+8,tg*2+1)
    const int g  = lane >> 2;
    const int tg = lane & 3;
#pragma unroll
    for (int i = 0; i < 4; i++) {
#pragma unroll
        for (int h2 = 0; h2 < 2; h2++) {
            int row = row0 + wm + i * 16 + g + h2 * 8;
            if (row >= rows) continue;
            if (MODE == 0) {
                size_t base = ((size_t)e * CAP + row) * FFNH;
#pragma unroll
                for (int j = 0; j < 4; j++) {
                    int c = col0 + wn + j * 8 + tg * 2;
                    float f0 = gelu_tanh(acc[i][j][h2 * 2 + 0]);
                    float f1 = gelu_tanh(acc[i][j][h2 * 2 + 1]);
                    unsigned short h0, l0, h1, l1;
                    split1h(f0, h0, l0);
                    split1h(f1, h1, l1);
                    *(uint32_t*)(g_h_hi + base + c) = (uint32_t)h0 | ((uint32_t)h1 << 16);
                    *(uint32_t*)(g_h_lo + base + c) = (uint32_t)l0 | ((uint32_t)l1 << 16);
                }
            } else {
                int   tok = g_tok[e * CAP + row];
                float gw  = g_prob[tok];
                float* dst = out + (size_t)tok * DMODEL;
#pragma unroll
                for (int j = 0; j < 4; j++) {
                    int c = col0 + wn + j * 8 + tg * 2;
                    float2 v;
                    v.x = acc[i][j][h2 * 2 + 0] * gw;
                    v.y = acc[i][j][h2 * 2 + 1] * gw;
                    *(float2*)(dst + c) = v;
                }
            }
        }
    }
}

// ---------------- launch ----------------
extern "C" void kernel_launch(void* const* d_in, const int* in_sizes, int n_in,
                              void* d_out, int out_size) {
    (void)in_sizes; (void)n_in;
    const float* x  = (const float*)d_in[0];   // [S, M]
    const float* Wg = (const float*)d_in[1];   // [M, E]
    const float* W1 = (const float*)d_in[2];   // [E, M, H]
    const float* W2 = (const float*)d_in[3];   // [E, H, M]
    float* out = (float*)d_out;                // [S, M]

    cudaFuncSetAttribute((const void*)moe_gemm_mma<0>,
                         cudaFuncAttributeMaxDynamicSharedMemorySize, SMEM_BYTES);
    cudaFuncSetAttribute((const void*)moe_gemm_mma<1>,
                         cudaFuncAttributeMaxDynamicSharedMemorySize, SMEM_BYTES);

    gate_kernel<<<TOKENS / 8, 256>>>(x, Wg);
    scan_kernel<<<1, 256>>>();
    split_x_kernel<<<(TOKENS * DMODEL) / (256 * 8), 256>>>(x);
    transpose_split_kernel<0><<<dim3(FFNH / 64, DMODEL / 64, NEXP), 256>>>(W1);
    transpose_split_kernel<1><<<dim3(DMODEL / 64, FFNH / 64, NEXP), 256>>>(W2);

    // grid.x = row tiles (fastest) so concurrent row-CTAs share each B tile in L2
    moe_gemm_mma<0><<<dim3(CAP / BM, FFNH / BN, NEXP), 256, SMEM_BYTES>>>(nullptr);
    cudaMemsetAsync(d_out, 0, (size_t)out_size * sizeof(float));   // dropped tokens -> 0
    moe_gemm_mma<1><<<dim3(CAP / BM, DMODEL / BN, NEXP), 256, SMEM_BYTES>>>(out);
}

// round 10
// speedup vs baseline: 2.5378x; 1.5652x over previous
#include <cuda_runtime.h>
#include <cuda_fp16.h>
#include <cstdint>
#include <math.h>

#define TOKENS 8192
#define DMODEL 2048
#define NEXP   8
#define FFNH   8192
#define CAP    2048

#define BM 128
#define BN 128
#define BK 64
#define STAGES 4
#define TILE_B  (BM * BK * 2)      /* 16384 bytes per operand tile */
#define OFF_A   0
#define OFF_B   (TILE_B)
#define STAGE_B (2 * TILE_B)       /* 32768 */
#define SMEM_BYTES (STAGES * STAGE_B)   /* 128 KB */

// ---------------- device scratch (no runtime allocation allowed) ----------------
__device__ int   g_idx[TOKENS];
__device__ float g_prob[TOKENS];
__device__ int   g_tok[NEXP * CAP];
__device__ int   g_count[NEXP];
__device__ __half g_x16[(size_t)TOKENS * DMODEL];
__device__ __half g_w1[(size_t)NEXP * FFNH * DMODEL];   // [e][h][m]  K-major
__device__ __half g_w2[(size_t)NEXP * DMODEL * FFNH];   // [e][m][h]  K-major
__device__ __half g_h[(size_t)NEXP * CAP * FFNH];       // [e][c][h]  K-major

// ---------------- helpers ----------------
__device__ __forceinline__ uint32_t smem_u32(const void* p) {
    uint32_t a;
    asm("{ .reg .u64 t; cvta.to.shared.u64 t, %1; cvt.u32.u64 %0, t; }" : "=r"(a) : "l"(p));
    return a;
}
__device__ __forceinline__ void cp16(uint32_t dst, const void* src, uint32_t sz) {
    asm volatile("cp.async.cg.shared.global [%0], [%1], 16, %2;"
                 :: "r"(dst), "l"(src), "r"(sz) : "memory");
}
#define CP_COMMIT() asm volatile("cp.async.commit_group;" ::: "memory")
#define CP_WAIT2()  asm volatile("cp.async.wait_group 2;" ::: "memory")
#define CP_WAIT0()  asm volatile("cp.async.wait_group 0;" ::: "memory")

__device__ __forceinline__ void ldsm_x4(uint32_t& r0, uint32_t& r1, uint32_t& r2,
                                        uint32_t& r3, uint32_t a) {
    asm volatile("ldmatrix.sync.aligned.m8n8.x4.shared.b16 {%0,%1,%2,%3}, [%4];"
                 : "=r"(r0), "=r"(r1), "=r"(r2), "=r"(r3) : "r"(a));
}
__device__ __forceinline__ void mma_f16(float* c, const uint32_t* a, const uint32_t* b) {
    asm volatile(
        "mma.sync.aligned.m16n8k16.row.col.f32.f16.f16.f32 "
        "{%0,%1,%2,%3}, {%4,%5,%6,%7}, {%8,%9}, {%0,%1,%2,%3};"
        : "+f"(c[0]), "+f"(c[1]), "+f"(c[2]), "+f"(c[3])
        : "r"(a[0]), "r"(a[1]), "r"(a[2]), "r"(a[3]), "r"(b[0]), "r"(b[1]));
}
__device__ __forceinline__ unsigned short cvt_h(float f) {
    return __half_as_ushort(__float2half_rn(f));
}
// jax.nn.gelu default: approximate=True (tanh form)
__device__ __forceinline__ float gelu_tanh(float v) {
    float c = 0.7978845608028654f * (v + 0.044715f * v * v * v);
    return 0.5f * v * (1.0f + tanhf(c));
}

// ---------------- gate: logits = x @ Wg, softmax, argmax (1 warp / token) ----------------
__global__ void gate_kernel(const float* __restrict__ x, const float* __restrict__ Wg) {
    int tokw = (blockIdx.x * blockDim.x + threadIdx.x) >> 5;
    int lane = threadIdx.x & 31;
    if (tokw >= TOKENS) return;
    const float* xr = x + (size_t)tokw * DMODEL;
    float acc[NEXP];
#pragma unroll
    for (int e = 0; e < NEXP; e++) acc[e] = 0.f;
    for (int m = lane; m < DMODEL; m += 32) {
        float xv = xr[m];
        float4 w0 = *(const float4*)(Wg + m * NEXP);
        float4 w1 = *(const float4*)(Wg + m * NEXP + 4);
        acc[0] = fmaf(xv, w0.x, acc[0]); acc[1] = fmaf(xv, w0.y, acc[1]);
        acc[2] = fmaf(xv, w0.z, acc[2]); acc[3] = fmaf(xv, w0.w, acc[3]);
        acc[4] = fmaf(xv, w1.x, acc[4]); acc[5] = fmaf(xv, w1.y, acc[5]);
        acc[6] = fmaf(xv, w1.z, acc[6]); acc[7] = fmaf(xv, w1.w, acc[7]);
    }
#pragma unroll
    for (int e = 0; e < NEXP; e++)
#pragma unroll
        for (int o = 16; o > 0; o >>= 1)
            acc[e] += __shfl_xor_sync(0xffffffffu, acc[e], o);
    if (lane == 0) {
        float mx = acc[0]; int am = 0;
#pragma unroll
        for (int e = 1; e < NEXP; e++)
            if (acc[e] > mx) { mx = acc[e]; am = e; }   // strict > = first max (jnp.argmax)
        float s = 0.f;
#pragma unroll
        for (int e = 0; e < NEXP; e++) s += expf(acc[e] - mx);
        g_idx[tokw]  = am;
        g_prob[tokw] = 1.0f / s;
    }
}

// ---------------- routing scan (order-preserving cumsum, warp w = expert w) ----------------
__global__ void scan_kernel() {
    int w = threadIdx.x >> 5, lane = threadIdx.x & 31;
    int count = 0;
    for (int base = 0; base < TOKENS; base += 32) {
        int t = base + lane;
        int match = (g_idx[t] == w);
        unsigned mask = __ballot_sync(0xffffffffu, match);
        if (match) {
            int p = count + __popc(mask & ((1u << lane) - 1u));
            if (p < CAP) g_tok[w * CAP + p] = t;
        }
        count += __popc(mask);
    }
    if (lane == 0) g_count[w] = (count < CAP) ? count : CAP;
}

// ---------------- prep: convert x -> fp16 ----------------
__global__ void cvt_x_kernel(const float* __restrict__ x) {
    size_t i = ((size_t)blockIdx.x * blockDim.x + threadIdx.x) * 8;
    float4 a = *(const float4*)(x + i);
    float4 b = *(const float4*)(x + i + 4);
    float v[8] = {a.x, a.y, a.z, a.w, b.x, b.y, b.z, b.w};
    uint4 hi;
    unsigned short* hp = (unsigned short*)&hi;
#pragma unroll
    for (int q = 0; q < 8; q++) hp[q] = cvt_h(v[q]);
    *(uint4*)(g_x16 + i) = hi;
}

// ---------------- prep: transpose + convert weights to K-major fp16 ----------------
// 64x64 tiles, paired fp16 writes (128B per warp store transaction).
// WHICH=0: W1 [e][M][H] -> g_w1 [e][H][M];  WHICH=1: W2 [e][H][M] -> g_w2 [e][M][H]
template <int WHICH>
__global__ void __launch_bounds__(256)
transpose_split_kernel(const float* __restrict__ in) {
    constexpr int Rin = (WHICH == 0) ? DMODEL : FFNH;   // input rows
    constexpr int Cin = (WHICH == 0) ? FFNH : DMODEL;   // input cols
    __half* ohi = (WHICH == 0) ? g_w1 : g_w2;
    __shared__ float t[64][65];
    const int e  = blockIdx.z;
    const float* ip = in + (size_t)e * Rin * Cin;
    const size_t ob = (size_t)e * Rin * Cin;
    const int c0 = blockIdx.x * 64, r0 = blockIdx.y * 64;
    const int tid = threadIdx.x;

    // read: 64 rows x 64 cols, float4 per thread per pass
    const int rr = tid >> 4;
    const int cc = (tid & 15) * 4;
#pragma unroll
    for (int i = 0; i < 4; i++) {
        int row = rr + i * 16;
        float4 v = *(const float4*)(ip + (size_t)(r0 + row) * Cin + c0 + cc);
        t[row][cc + 0] = v.x; t[row][cc + 1] = v.y;
        t[row][cc + 2] = v.z; t[row][cc + 3] = v.w;
    }
    __syncthreads();

    // write: warp w owns output row p*8+w; lane packs 2 consecutive fp16 (4B store)
    const int w = tid >> 5, l = tid & 31;
#pragma unroll
    for (int p = 0; p < 8; p++) {
        int orow = p * 8 + w;                 // source column
        unsigned short h0 = cvt_h(t[2 * l][orow]);
        unsigned short h1 = cvt_h(t[2 * l + 1][orow]);
        size_t o = ob + (size_t)(c0 + orow) * Rin + r0 + 2 * l;
        *(uint32_t*)(ohi + o) = (uint32_t)h0 | ((uint32_t)h1 << 16);
    }
}

// ---------------- grouped GEMM, HMMA fp16 single-pass ----------------
// CTA tile 128x128, warp tile 64x32, 4-stage cp.async pipeline (prefetch dist 3).
// MODE 0: h[e] = gelu( gather(x16) @ W1[e] )   K=2048, N=8192
// MODE 1: out[tok] = ( h @ W2[e] ) * prob      K=8192, N=2048
template <int MODE>
__global__ void __launch_bounds__(256, 1)
moe_gemm_mma(float* __restrict__ out) {
    constexpr int Ktot = (MODE == 0) ? DMODEL : FFNH;
    constexpr int nK   = Ktot / BK;

    extern __shared__ char smem[];
    const uint32_t sb = smem_u32(smem);
    const int tid  = threadIdx.x;
    const int lane = tid & 31;
    const int wid  = tid >> 5;
    const int e    = blockIdx.z;
    const int rows = g_count[e];
    const int row0 = blockIdx.x * BM;
    if (row0 >= rows) return;                 // count-limited: skip empty tiles
    const int col0 = blockIdx.y * BN;

    // ---- loader: thread -> smem row (tid>>1), 64-byte half (tid&1) ----
    const int lrow = tid >> 1;
    const int half = tid & 1;
    uint32_t swo[4];
#pragma unroll
    for (int j = 0; j < 4; j++) {
        uint32_t u = (uint32_t)(half * 4 + j);
        swo[j] = (uint32_t)lrow * 128u + ((u ^ ((uint32_t)lrow & 7u)) << 4);
    }
    const int  gr     = row0 + lrow;
    const bool avalid = gr < rows;
    const uint32_t asz = avalid ? 16u : 0u;
    const char *pA, *pB;
    if (MODE == 0) {
        int tok = avalid ? g_tok[e * CAP + gr] : 0;
        pA = (const char*)(g_x16 + (size_t)tok * DMODEL) + half * 64;
        pB = (const char*)(g_w1 + ((size_t)e * FFNH + col0 + lrow) * DMODEL) + half * 64;
    } else {
        pA = (const char*)(g_h + ((size_t)e * CAP + gr) * FFNH) + half * 64;
        pB = (const char*)(g_w2 + ((size_t)e * DMODEL + col0 + lrow) * FFNH) + half * 64;
    }

    auto load_stage = [&](int kt) {
        uint32_t s = sb + (uint32_t)(kt % STAGES) * STAGE_B;
        size_t go = (size_t)kt * (BK * 2);          // byte offset along K
#pragma unroll
        for (int j = 0; j < 4; j++) cp16(s + OFF_A + swo[j], pA + go + j * 16, asz);
#pragma unroll
        for (int j = 0; j < 4; j++) cp16(s + OFF_B + swo[j], pB + go + j * 16, 16u);
    };

    load_stage(0); CP_COMMIT();
    load_stage(1); CP_COMMIT();
    load_stage(2); CP_COMMIT();

    // ---- warp tiling: 2 (m) x 4 (n), warp tile 64x32 ----
    const int wm = (wid & 1) * 64;
    const int wn = (wid >> 1) * 32;

    // ldmatrix per-thread address pieces
    const int a_rloc = ((lane >> 3) & 1) * 8 + (lane & 7);   // row within 16-row m-tile
    const int a_kub  = lane >> 4;                            // 0/1: k-unit selector
    // B x4 pairing: lanes 0-7 -> (n-tile j, u0), 8-15 -> (j, u1),
    //               16-23 -> (j+1, u0), 24-31 -> (j+1, u1)
    const int b_jj   = lane >> 4;
    const int b_ku   = (lane >> 3) & 1;
    const int b_rloc = lane & 7;

    float acc[4][4][4];
#pragma unroll
    for (int i = 0; i < 4; i++)
#pragma unroll
        for (int j = 0; j < 4; j++)
#pragma unroll
            for (int q = 0; q < 4; q++) acc[i][j][q] = 0.f;

    for (int kt = 0; kt < nK; kt++) {
        CP_WAIT2();                      // stage kt arrived (<=2 groups pending)
        __syncthreads();
        if (kt + 3 < nK) load_stage(kt + 3);
        CP_COMMIT();

        const uint32_t s = sb + (uint32_t)(kt % STAGES) * STAGE_B;
#pragma unroll
        for (int ks = 0; ks < BK / 16; ks++) {
            uint32_t ah[4][4];
#pragma unroll
            for (int i = 0; i < 4; i++) {
                int row = wm + i * 16 + a_rloc;
                int u   = ks * 2 + a_kub;
                uint32_t off = (uint32_t)row * 128u + (((uint32_t)u ^ ((uint32_t)row & 7u)) << 4);
                ldsm_x4(ah[i][0], ah[i][1], ah[i][2], ah[i][3], s + OFF_A + off);
            }
            uint32_t bh[4][2];
#pragma unroll
            for (int jp = 0; jp < 2; jp++) {      // n-tile pairs {0,1} and {2,3}
                int j   = jp * 2;
                int row = wn + (j + b_jj) * 8 + b_rloc;
                int u   = ks * 2 + b_ku;
                uint32_t off = (uint32_t)row * 128u + (((uint32_t)u ^ ((uint32_t)row & 7u)) << 4);
                ldsm_x4(bh[j][0], bh[j][1], bh[j + 1][0], bh[j + 1][1], s + OFF_B + off);
            }
#pragma unroll
            for (int i = 0; i < 4; i++)
#pragma unroll
                for (int j = 0; j < 4; j++) mma_f16(acc[i][j], ah[i], bh[j]);
        }
    }
    CP_WAIT0();

    // ---- epilogue (register accumulators) ----
    // frag layout: c0=(m=g,n=tg*2) c1=(g,tg*2+1) c2=(g+8,tg*2) c3=(g+8,tg*2+1)
    const int g  = lane >> 2;
    const int tg = lane & 3;
#pragma unroll
    for (int i = 0; i < 4; i++) {
#pragma unroll
        for (int h2 = 0; h2 < 2; h2++) {
            int row = row0 + wm + i * 16 + g + h2 * 8;
            if (row >= rows) continue;
            if (MODE == 0) {
                size_t base = ((size_t)e * CAP + row) * FFNH;
#pragma unroll
                for (int j = 0; j < 4; j++) {
                    int c = col0 + wn + j * 8 + tg * 2;
                    unsigned short h0 = cvt_h(gelu_tanh(acc[i][j][h2 * 2 + 0]));
                    unsigned short h1 = cvt_h(gelu_tanh(acc[i][j][h2 * 2 + 1]));
                    *(uint32_t*)(g_h + base + c) = (uint32_t)h0 | ((uint32_t)h1 << 16);
                }
            } else {
                int   tok = g_tok[e * CAP + row];
                float gw  = g_prob[tok];
                float* dst = out + (size_t)tok * DMODEL;
#pragma unroll
                for (int j = 0; j < 4; j++) {
                    int c = col0 + wn + j * 8 + tg * 2;
                    float2 v;
                    v.x = acc[i][j][h2 * 2 + 0] * gw;
                    v.y = acc[i][j][h2 * 2 + 1] * gw;
                    *(float2*)(dst + c) = v;
                }
            }
        }
    }
}

// ---------------- launch ----------------
extern "C" void kernel_launch(void* const* d_in, const int* in_sizes, int n_in,
                              void* d_out, int out_size) {
    (void)in_sizes; (void)n_in;
    const float* x  = (const float*)d_in[0];   // [S, M]
    const float* Wg = (const float*)d_in[1];   // [M, E]
    const float* W1 = (const float*)d_in[2];   // [E, M, H]
    const float* W2 = (const float*)d_in[3];   // [E, H, M]
    float* out = (float*)d_out;                // [S, M]

    cudaFuncSetAttribute((const void*)moe_gemm_mma<0>,
                         cudaFuncAttributeMaxDynamicSharedMemorySize, SMEM_BYTES);
    cudaFuncSetAttribute((const void*)moe_gemm_mma<1>,
                         cudaFuncAttributeMaxDynamicSharedMemorySize, SMEM_BYTES);

    gate_kernel<<<TOKENS / 8, 256>>>(x, Wg);
    scan_kernel<<<1, 256>>>();
    cvt_x_kernel<<<(TOKENS * DMODEL) / (256 * 8), 256>>>(x);
    transpose_split_kernel<0><<<dim3(FFNH / 64, DMODEL / 64, NEXP), 256>>>(W1);
    transpose_split_kernel<1><<<dim3(DMODEL / 64, FFNH / 64, NEXP), 256>>>(W2);

    // grid.x = row tiles (fastest) so concurrent row-CTAs share each B tile in L2
    moe_gemm_mma<0><<<dim3(CAP / BM, FFNH / BN, NEXP), 256, SMEM_BYTES>>>(nullptr);
    cudaMemsetAsync(d_out, 0, (size_t)out_size * sizeof(float));   // dropped tokens -> 0
    moe_gemm_mma<1><<<dim3(CAP / BM, DMODEL / BN, NEXP), 256, SMEM_BYTES>>>(out);
}

// round 11
// speedup vs baseline: 3.0469x; 1.2006x over previous
#include <cuda_runtime.h>
#include <cuda_fp16.h>
#include <cstdint>
#include <math.h>

#define TOKENS 8192
#define DMODEL 2048
#define NEXP   8
#define FFNH   8192
#define CAP    2048

#define BM 128
#define BN 256
#define BK 64
#define STAGES 4
#define TILE_A  (BM * BK * 2)      /* 16384 */
#define TILE_BB (BN * BK * 2)      /* 32768 */
#define OFF_A   0
#define OFF_B   (TILE_A)
#define STAGE_B (TILE_A + TILE_BB) /* 49152 */
#define SMEM_BYTES (STAGES * STAGE_B)   /* 192 KB */

// ---------------- device scratch (no runtime allocation allowed) ----------------
__device__ int   g_idx[TOKENS];
__device__ float g_prob[TOKENS];
__device__ int   g_tok[NEXP * CAP];
__device__ int   g_count[NEXP];
__device__ __half g_x16[(size_t)TOKENS * DMODEL];
__device__ __half g_w1[(size_t)NEXP * FFNH * DMODEL];   // [e][h][m]  K-major
__device__ __half g_w2[(size_t)NEXP * DMODEL * FFNH];   // [e][m][h]  K-major
__device__ __half g_h[(size_t)NEXP * CAP * FFNH];       // [e][c][h]  K-major

// ---------------- helpers ----------------
__device__ __forceinline__ uint32_t smem_u32(const void* p) {
    uint32_t a;
    asm("{ .reg .u64 t; cvta.to.shared.u64 t, %1; cvt.u32.u64 %0, t; }" : "=r"(a) : "l"(p));
    return a;
}
__device__ __forceinline__ void cp16(uint32_t dst, const void* src, uint32_t sz) {
    asm volatile("cp.async.cg.shared.global [%0], [%1], 16, %2;"
                 :: "r"(dst), "l"(src), "r"(sz) : "memory");
}
#define CP_COMMIT() asm volatile("cp.async.commit_group;" ::: "memory")
#define CP_WAIT2()  asm volatile("cp.async.wait_group 2;" ::: "memory")
#define CP_WAIT0()  asm volatile("cp.async.wait_group 0;" ::: "memory")

__device__ __forceinline__ void ldsm_x4(uint32_t& r0, uint32_t& r1, uint32_t& r2,
                                        uint32_t& r3, uint32_t a) {
    asm volatile("ldmatrix.sync.aligned.m8n8.x4.shared.b16 {%0,%1,%2,%3}, [%4];"
                 : "=r"(r0), "=r"(r1), "=r"(r2), "=r"(r3) : "r"(a));
}
__device__ __forceinline__ void mma_f16(float* c, const uint32_t* a, const uint32_t* b) {
    asm volatile(
        "mma.sync.aligned.m16n8k16.row.col.f32.f16.f16.f32 "
        "{%0,%1,%2,%3}, {%4,%5,%6,%7}, {%8,%9}, {%0,%1,%2,%3};"
        : "+f"(c[0]), "+f"(c[1]), "+f"(c[2]), "+f"(c[3])
        : "r"(a[0]), "r"(a[1]), "r"(a[2]), "r"(a[3]), "r"(b[0]), "r"(b[1]));
}
__device__ __forceinline__ unsigned short cvt_h(float f) {
    return __half_as_ushort(__float2half_rn(f));
}
// jax.nn.gelu default: approximate=True (tanh form)
__device__ __forceinline__ float gelu_tanh(float v) {
    float c = 0.7978845608028654f * (v + 0.044715f * v * v * v);
    return 0.5f * v * (1.0f + tanhf(c));
}

// ---------------- gate: logits = x @ Wg, softmax, argmax (1 warp / token) ----------------
__global__ void gate_kernel(const float* __restrict__ x, const float* __restrict__ Wg) {
    int tokw = (blockIdx.x * blockDim.x + threadIdx.x) >> 5;
    int lane = threadIdx.x & 31;
    if (tokw >= TOKENS) return;
    const float* xr = x + (size_t)tokw * DMODEL;
    float acc[NEXP];
#pragma unroll
    for (int e = 0; e < NEXP; e++) acc[e] = 0.f;
    for (int m = lane; m < DMODEL; m += 32) {
        float xv = xr[m];
        float4 w0 = *(const float4*)(Wg + m * NEXP);
        float4 w1 = *(const float4*)(Wg + m * NEXP + 4);
        acc[0] = fmaf(xv, w0.x, acc[0]); acc[1] = fmaf(xv, w0.y, acc[1]);
        acc[2] = fmaf(xv, w0.z, acc[2]); acc[3] = fmaf(xv, w0.w, acc[3]);
        acc[4] = fmaf(xv, w1.x, acc[4]); acc[5] = fmaf(xv, w1.y, acc[5]);
        acc[6] = fmaf(xv, w1.z, acc[6]); acc[7] = fmaf(xv, w1.w, acc[7]);
    }
#pragma unroll
    for (int e = 0; e < NEXP; e++)
#pragma unroll
        for (int o = 16; o > 0; o >>= 1)
            acc[e] += __shfl_xor_sync(0xffffffffu, acc[e], o);
    if (lane == 0) {
        float mx = acc[0]; int am = 0;
#pragma unroll
        for (int e = 1; e < NEXP; e++)
            if (acc[e] > mx) { mx = acc[e]; am = e; }   // strict > = first max (jnp.argmax)
        float s = 0.f;
#pragma unroll
        for (int e = 0; e < NEXP; e++) s += expf(acc[e] - mx);
        g_idx[tokw]  = am;
        g_prob[tokw] = 1.0f / s;
    }
}

// ---------------- routing scan (order-preserving cumsum, warp w = expert w) ----------------
__global__ void scan_kernel() {
    int w = threadIdx.x >> 5, lane = threadIdx.x & 31;
    int count = 0;
    for (int base = 0; base < TOKENS; base += 32) {
        int t = base + lane;
        int match = (g_idx[t] == w);
        unsigned mask = __ballot_sync(0xffffffffu, match);
        if (match) {
            int p = count + __popc(mask & ((1u << lane) - 1u));
            if (p < CAP) g_tok[w * CAP + p] = t;
        }
        count += __popc(mask);
    }
    if (lane == 0) g_count[w] = (count < CAP) ? count : CAP;
}

// ---------------- prep: convert x -> fp16 ----------------
__global__ void cvt_x_kernel(const float* __restrict__ x) {
    size_t i = ((size_t)blockIdx.x * blockDim.x + threadIdx.x) * 8;
    float4 a = *(const float4*)(x + i);
    float4 b = *(const float4*)(x + i + 4);
    float v[8] = {a.x, a.y, a.z, a.w, b.x, b.y, b.z, b.w};
    uint4 hi;
    unsigned short* hp = (unsigned short*)&hi;
#pragma unroll
    for (int q = 0; q < 8; q++) hp[q] = cvt_h(v[q]);
    *(uint4*)(g_x16 + i) = hi;
}

// ---------------- prep: transpose + convert weights to K-major fp16 ----------------
// 64x64 tiles, paired fp16 writes (128B per warp store transaction).
// WHICH=0: W1 [e][M][H] -> g_w1 [e][H][M];  WHICH=1: W2 [e][H][M] -> g_w2 [e][M][H]
template <int WHICH>
__global__ void __launch_bounds__(256)
transpose_split_kernel(const float* __restrict__ in) {
    constexpr int Rin = (WHICH == 0) ? DMODEL : FFNH;   // input rows
    constexpr int Cin = (WHICH == 0) ? FFNH : DMODEL;   // input cols
    __half* ohi = (WHICH == 0) ? g_w1 : g_w2;
    __shared__ float t[64][65];
    const int e  = blockIdx.z;
    const float* ip = in + (size_t)e * Rin * Cin;
    const size_t ob = (size_t)e * Rin * Cin;
    const int c0 = blockIdx.x * 64, r0 = blockIdx.y * 64;
    const int tid = threadIdx.x;

    // read: 64 rows x 64 cols, float4 per thread per pass
    const int rr = tid >> 4;
    const int cc = (tid & 15) * 4;
#pragma unroll
    for (int i = 0; i < 4; i++) {
        int row = rr + i * 16;
        float4 v = *(const float4*)(ip + (size_t)(r0 + row) * Cin + c0 + cc);
        t[row][cc + 0] = v.x; t[row][cc + 1] = v.y;
        t[row][cc + 2] = v.z; t[row][cc + 3] = v.w;
    }
    __syncthreads();

    // write: warp w owns output row p*8+w; lane packs 2 consecutive fp16 (4B store)
    const int w = tid >> 5, l = tid & 31;
#pragma unroll
    for (int p = 0; p < 8; p++) {
        int orow = p * 8 + w;                 // source column
        unsigned short h0 = cvt_h(t[2 * l][orow]);
        unsigned short h1 = cvt_h(t[2 * l + 1][orow]);
        size_t o = ob + (size_t)(c0 + orow) * Rin + r0 + 2 * l;
        *(uint32_t*)(ohi + o) = (uint32_t)h0 | ((uint32_t)h1 << 16);
    }
}

// ---------------- grouped GEMM, HMMA fp16 single-pass ----------------
// CTA tile 128x256, 512 threads (16 warps, 2m x 8n, warp tile 64x32),
// 4-stage cp.async pipeline (prefetch dist 3) — proven R10 skeleton widened in N.
// MODE 0: h[e] = gelu( gather(x16) @ W1[e] )   K=2048, N=8192
// MODE 1: out[tok] = ( h @ W2[e] ) * prob      K=8192, N=2048
template <int MODE>
__global__ void __launch_bounds__(512, 1)
moe_gemm_mma(float* __restrict__ out) {
    constexpr int Ktot = (MODE == 0) ? DMODEL : FFNH;
    constexpr int nK   = Ktot / BK;

    extern __shared__ char smem[];
    const uint32_t sb = smem_u32(smem);
    const int tid  = threadIdx.x;
    const int lane = tid & 31;
    const int wid  = tid >> 5;
    const int e    = blockIdx.z;
    const int rows = g_count[e];
    const int row0 = blockIdx.x * BM;
    if (row0 >= rows) return;                 // count-limited: skip empty tiles
    const int col0 = blockIdx.y * BN;

    // ---- A loader: thread -> A row (tid>>2), 2 units at (tid&3)*2 ----
    const int ar = tid >> 2;
    const int au = (tid & 3) * 2;
    uint32_t aswo[2];
#pragma unroll
    for (int j = 0; j < 2; j++) {
        uint32_t u = (uint32_t)(au + j);
        aswo[j] = (uint32_t)ar * 128u + ((u ^ ((uint32_t)ar & 7u)) << 4);
    }
    // ---- B loader: thread -> B row (tid>>1), 4 units at (tid&1)*4 ----
    const int br = tid >> 1;
    const int bu = (tid & 1) * 4;
    uint32_t bswo[4];
#pragma unroll
    for (int j = 0; j < 4; j++) {
        uint32_t u = (uint32_t)(bu + j);
        bswo[j] = (uint32_t)br * 128u + ((u ^ ((uint32_t)br & 7u)) << 4);
    }

    const int  gr     = row0 + ar;
    const bool avalid = gr < rows;
    const uint32_t asz = avalid ? 16u : 0u;
    const char *pA, *pB;
    if (MODE == 0) {
        int tok = avalid ? g_tok[e * CAP + gr] : 0;
        pA = (const char*)(g_x16 + (size_t)tok * DMODEL);
        pB = (const char*)(g_w1 + ((size_t)e * FFNH + col0 + br) * DMODEL);
    } else {
        pA = (const char*)(g_h + ((size_t)e * CAP + gr) * FFNH);
        pB = (const char*)(g_w2 + ((size_t)e * DMODEL + col0 + br) * FFNH);
    }

    auto load_stage = [&](int kt) {
        uint32_t s = sb + (uint32_t)(kt % STAGES) * STAGE_B;
        size_t go = (size_t)kt * (BK * 2);          // byte offset along K
#pragma unroll
        for (int j = 0; j < 2; j++) cp16(s + OFF_A + aswo[j], pA + go + (au + j) * 16, asz);
#pragma unroll
        for (int j = 0; j < 4; j++) cp16(s + OFF_B + bswo[j], pB + go + (bu + j) * 16, 16u);
    };

    load_stage(0); CP_COMMIT();
    load_stage(1); CP_COMMIT();
    load_stage(2); CP_COMMIT();

    // ---- warp tiling: 2 (m) x 8 (n), warp tile 64x32 ----
    const int wm = (wid & 1) * 64;
    const int wn = (wid >> 1) * 32;

    // ldmatrix per-thread address pieces
    const int a_rloc = ((lane >> 3) & 1) * 8 + (lane & 7);   // row within 16-row m-tile
    const int a_kub  = lane >> 4;                            // 0/1: k-unit selector
    // B x4 pairing: lanes 0-7 -> (n-tile j, u0), 8-15 -> (j, u1),
    //               16-23 -> (j+1, u0), 24-31 -> (j+1, u1)
    const int b_jj   = lane >> 4;
    const int b_ku   = (lane >> 3) & 1;
    const int b_rloc = lane & 7;

    float acc[4][4][4];
#pragma unroll
    for (int i = 0; i < 4; i++)
#pragma unroll
        for (int j = 0; j < 4; j++)
#pragma unroll
            for (int q = 0; q < 4; q++) acc[i][j][q] = 0.f;

    for (int kt = 0; kt < nK; kt++) {
        CP_WAIT2();                      // stage kt arrived (<=2 groups pending)
        __syncthreads();
        if (kt + 3 < nK) load_stage(kt + 3);
        CP_COMMIT();

        const uint32_t s = sb + (uint32_t)(kt % STAGES) * STAGE_B;
#pragma unroll
        for (int ks = 0; ks < BK / 16; ks++) {
            uint32_t ah[4][4];
#pragma unroll
            for (int i = 0; i < 4; i++) {
                int row = wm + i * 16 + a_rloc;
                int u   = ks * 2 + a_kub;
                uint32_t off = (uint32_t)row * 128u + (((uint32_t)u ^ ((uint32_t)row & 7u)) << 4);
                ldsm_x4(ah[i][0], ah[i][1], ah[i][2], ah[i][3], s + OFF_A + off);
            }
            uint32_t bh[4][2];
#pragma unroll
            for (int jp = 0; jp < 2; jp++) {      // n-tile pairs {0,1} and {2,3}
                int j   = jp * 2;
                int row = wn + (j + b_jj) * 8 + b_rloc;
                int u   = ks * 2 + b_ku;
                uint32_t off = (uint32_t)row * 128u + (((uint32_t)u ^ ((uint32_t)row & 7u)) << 4);
                ldsm_x4(bh[j][0], bh[j][1], bh[j + 1][0], bh[j + 1][1], s + OFF_B + off);
            }
#pragma unroll
            for (int i = 0; i < 4; i++)
#pragma unroll
                for (int j = 0; j < 4; j++) mma_f16(acc[i][j], ah[i], bh[j]);
        }
    }
    CP_WAIT0();

    // ---- epilogue (register accumulators) ----
    // frag layout: c0=(m=g,n=tg*2) c1=(g,tg*2+1) c2=(g+8,tg*2) c3=(g+8,tg*2+1)
    const int g  = lane >> 2;
    const int tg = lane & 3;
#pragma unroll
    for (int i = 0; i < 4; i++) {
#pragma unroll
        for (int h2 = 0; h2 < 2; h2++) {
            int row = row0 + wm + i * 16 + g + h2 * 8;
            if (row >= rows) continue;
            if (MODE == 0) {
                size_t base = ((size_t)e * CAP + row) * FFNH;
#pragma unroll
                for (int j = 0; j < 4; j++) {
                    int c = col0 + wn + j * 8 + tg * 2;
                    unsigned short h0 = cvt_h(gelu_tanh(acc[i][j][h2 * 2 + 0]));
                    unsigned short h1 = cvt_h(gelu_tanh(acc[i][j][h2 * 2 + 1]));
                    *(uint32_t*)(g_h + base + c) = (uint32_t)h0 | ((uint32_t)h1 << 16);
                }
            } else {
                int   tok = g_tok[e * CAP + row];
                float gw  = g_prob[tok];
                float* dst = out + (size_t)tok * DMODEL;
#pragma unroll
                for (int j = 0; j < 4; j++) {
                    int c = col0 + wn + j * 8 + tg * 2;
                    float2 v;
                    v.x = acc[i][j][h2 * 2 + 0] * gw;
                    v.y = acc[i][j][h2 * 2 + 1] * gw;
                    *(float2*)(dst + c) = v;
                }
            }
        }
    }
}

// ---------------- launch ----------------
extern "C" void kernel_launch(void* const* d_in, const int* in_sizes, int n_in,
                              void* d_out, int out_size) {
    (void)in_sizes; (void)n_in;
    const float* x  = (const float*)d_in[0];   // [S, M]
    const float* Wg = (const float*)d_in[1];   // [M, E]
    const float* W1 = (const float*)d_in[2];   // [E, M, H]
    const float* W2 = (const float*)d_in[3];   // [E, H, M]
    float* out = (float*)d_out;                // [S, M]

    cudaFuncSetAttribute((const void*)moe_gemm_mma<0>,
                         cudaFuncAttributeMaxDynamicSharedMemorySize, SMEM_BYTES);
    cudaFuncSetAttribute((const void*)moe_gemm_mma<1>,
                         cudaFuncAttributeMaxDynamicSharedMemorySize, SMEM_BYTES);

    gate_kernel<<<TOKENS / 8, 256>>>(x, Wg);
    scan_kernel<<<1, 256>>>();
    cvt_x_kernel<<<(TOKENS * DMODEL) / (256 * 8), 256>>>(x);
    transpose_split_kernel<0><<<dim3(FFNH / 64, DMODEL / 64, NEXP), 256>>>(W1);
    transpose_split_kernel<1><<<dim3(DMODEL / 64, FFNH / 64, NEXP), 256>>>(W2);

    // grid.x = row tiles (fastest) so concurrent row-CTAs share each B tile in L2
    moe_gemm_mma<0><<<dim3(CAP / BM, FFNH / BN, NEXP), 512, SMEM_BYTES>>>(nullptr);
    cudaMemsetAsync(d_out, 0, (size_t)out_size * sizeof(float));   // dropped tokens -> 0
    moe_gemm_mma<1><<<dim3(CAP / BM, DMODEL / BN, NEXP), 512, SMEM_BYTES>>>(out);
}